// round 1
// baseline (speedup 1.0000x reference)
#include <cuda_runtime.h>
#include <math.h>

#define D_TOT 320
#define DZ    64
#define DX    256
#define HID   16
#define BATCH 1024
#define NEG   0.01f
#define HALF_LOG2PI 0.91893853320467274f

// scratch (device globals — no allocation allowed)
__device__ float g_E[D_TOT * D_TOT];            // exp(-mask_param)
__device__ float g_W0z[D_TOT * D_TOT * HID];    // W0 with diag (j==k) zeroed
__device__ float g_accum;                       // recons accumulator

__device__ __forceinline__ float lrelu(float v) { return fmaxf(v, NEG * v); }

// ---------------------------------------------------------------------------
// Init: E = exp(-mask_param), W0 diag-zero copy, std -> out, zero accumulator
// ---------------------------------------------------------------------------
__global__ void init_kernel(const float* __restrict__ mp,
                            const float* __restrict__ W0,
                            const float* __restrict__ logvar,
                            float* __restrict__ out) {
    int i = blockIdx.x * blockDim.x + threadIdx.x;
    if (i < D_TOT * D_TOT) g_E[i] = expf(-mp[i]);
    if (i < D_TOT * D_TOT * HID) {
        int k = i / (D_TOT * HID);
        int j = (i / HID) % D_TOT;
        g_W0z[i] = (j == k) ? 0.0f : W0[i];
    }
    if (i < D_TOT) out[1 + BATCH * D_TOT + i] = expf(0.5f * logvar[i]);
    if (i == 0) g_accum = 0.0f;
}

// ---------------------------------------------------------------------------
// Latent path: k < 64, only j == k contributes (fixed-mask self-link)
// one thread per (b, k)
// ---------------------------------------------------------------------------
__global__ void latent_kernel(const float* __restrict__ z,
                              const float* __restrict__ u,
                              const float* __restrict__ W0,
                              const float* __restrict__ b0,
                              const float* __restrict__ W1,
                              const float* __restrict__ b1,
                              const float* __restrict__ W2,
                              const float* __restrict__ b2,
                              const float* __restrict__ logvar,
                              float* __restrict__ out) {
    int tid = blockIdx.x * blockDim.x + threadIdx.x;   // 65536 = 1024*64
    int k = tid & (DZ - 1);
    int b = tid >> 6;

    float uu = u[((size_t)b * D_TOT + k) * D_TOT + k];
    float E  = g_E[k * D_TOT + k];
    float s  = z[b * DZ + k];
    float denom = fmaf(1.0f - uu, E, uu);
    float m = __fdividef(uu * s, denom);

    float h1v[HID];
#pragma unroll
    for (int g = 0; g < HID; g++) h1v[g] = b1[k * HID + g];
#pragma unroll
    for (int h = 0; h < HID; h++) {
        float h0 = fmaf(m, W0[((size_t)k * D_TOT + k) * HID + h], b0[k * HID + h]);
        float a = lrelu(h0);
        const float* w1r = W1 + (k * HID + h) * HID;
#pragma unroll
        for (int g = 0; g < HID; g++) h1v[g] = fmaf(a, w1r[g], h1v[g]);
    }
    float mu = b2[k];
#pragma unroll
    for (int h = 0; h < HID; h++) mu = fmaf(lrelu(h1v[h]), W2[k * HID + h], mu);

    out[1 + (size_t)b * D_TOT + k] = mu;

    float logstd = 0.5f * logvar[k];
    float istd = __expf(-logstd);
    float diff = (s - mu) * istd;
    float lp = fmaf(-0.5f * diff, diff, -logstd - HALF_LOG2PI);

#pragma unroll
    for (int o = 16; o > 0; o >>= 1) lp += __shfl_down_sync(0xffffffffu, lp, o);
    if ((threadIdx.x & 31) == 0) atomicAdd(&g_accum, lp);
}

// ---------------------------------------------------------------------------
// Dense path: k in [64, 320). Block: 32 k (lanes) x 32 b (8 warps x 4 b/thread)
// ---------------------------------------------------------------------------
__global__ void __launch_bounds__(256, 2)
dense_kernel(const float* __restrict__ x,
             const float* __restrict__ z,
             const float* __restrict__ u,
             const float* __restrict__ b0,
             const float* __restrict__ W1,
             const float* __restrict__ b1,
             const float* __restrict__ W2,
             const float* __restrict__ b2,
             const float* __restrict__ logvar,
             float* __restrict__ out) {
    __shared__ float ss[32 * D_TOT];            // all_var for this block's 32 b's

    int tid  = threadIdx.x;
    int lane = tid & 31;
    int warp = tid >> 5;
    int k = DZ + blockIdx.x * 32 + lane;        // this lane's variable index
    int bbase = blockIdx.y * 32 + warp * 4;     // 4 consecutive b's per thread

    // stage all_var = concat(z, x) into smem (coalesced gmem reads)
    for (int idx = tid; idx < 32 * D_TOT; idx += 256) {
        int bl = idx / D_TOT;
        int j  = idx - bl * D_TOT;
        int b  = blockIdx.y * 32 + bl;
        ss[idx] = (j < DZ) ? z[b * DZ + j] : x[b * DX + (j - DZ)];
    }
    __syncthreads();

    float acc[4][HID];
#pragma unroll
    for (int i = 0; i < 4; i++)
#pragma unroll
        for (int h = 0; h < HID; h++) acc[i][h] = b0[k * HID + h];

    const float* srow = &ss[(warp * 4) * D_TOT];

    for (int j0 = 0; j0 < D_TOT; j0 += 16) {
#pragma unroll 2
        for (int jj = 0; jj < 16; jj++) {
            int j = j0 + jj;
            float E = g_E[j * D_TOT + k];
            const float4* wp = (const float4*)(g_W0z + ((size_t)k * D_TOT + j) * HID);
            float4 q0 = wp[0], q1 = wp[1], q2 = wp[2], q3 = wp[3];
            float wv[HID] = {q0.x, q0.y, q0.z, q0.w, q1.x, q1.y, q1.z, q1.w,
                             q2.x, q2.y, q2.z, q2.w, q3.x, q3.y, q3.z, q3.w};
#pragma unroll
            for (int i = 0; i < 4; i++) {
                float sj = srow[i * D_TOT + j];
                float uu = u[((size_t)(bbase + i) * D_TOT + j) * D_TOT + k];
                float denom = fmaf(1.0f - uu, E, uu);
                float m = __fdividef(uu * sj, denom);
#pragma unroll
                for (int h = 0; h < HID; h++) acc[i][h] = fmaf(m, wv[h], acc[i][h]);
            }
        }
        __syncthreads();   // keep 8 warps' W0/E window hot in L1
    }

    // epilogue: layers 1 & 2, mu, logp
    float logstd = 0.5f * logvar[k];
    float istd = __expf(-logstd);
    float lpsum = 0.0f;

#pragma unroll
    for (int i = 0; i < 4; i++) {
        float h1v[HID];
#pragma unroll
        for (int g = 0; g < HID; g++) h1v[g] = b1[k * HID + g];
#pragma unroll
        for (int h = 0; h < HID; h++) {
            float a = lrelu(acc[i][h]);
            const float4* w1p = (const float4*)(W1 + ((size_t)k * HID + h) * HID);
            float4 r0 = w1p[0], r1 = w1p[1], r2 = w1p[2], r3 = w1p[3];
            float wr[HID] = {r0.x, r0.y, r0.z, r0.w, r1.x, r1.y, r1.z, r1.w,
                             r2.x, r2.y, r2.z, r2.w, r3.x, r3.y, r3.z, r3.w};
#pragma unroll
            for (int g = 0; g < HID; g++) h1v[g] = fmaf(a, wr[g], h1v[g]);
        }
        float mu = b2[k];
#pragma unroll
        for (int h = 0; h < HID; h++) mu = fmaf(lrelu(h1v[h]), W2[k * HID + h], mu);

        int b = bbase + i;
        out[1 + (size_t)b * D_TOT + k] = mu;

        float sk = ss[(warp * 4 + i) * D_TOT + k];
        float diff = (sk - mu) * istd;
        lpsum += fmaf(-0.5f * diff, diff, -logstd - HALF_LOG2PI);
    }

#pragma unroll
    for (int o = 16; o > 0; o >>= 1) lpsum += __shfl_down_sync(0xffffffffu, lpsum, o);
    if (lane == 0) atomicAdd(&g_accum, lpsum);
}

// ---------------------------------------------------------------------------
__global__ void finalize_kernel(float* __restrict__ out) {
    if (threadIdx.x == 0 && blockIdx.x == 0)
        out[0] = g_accum * (1.0f / (float)BATCH);
}

// ---------------------------------------------------------------------------
extern "C" void kernel_launch(void* const* d_in, const int* in_sizes, int n_in,
                              void* d_out, int out_size) {
    const float* x      = (const float*)d_in[0];
    const float* z      = (const float*)d_in[1];
    const float* u      = (const float*)d_in[2];
    const float* mp     = (const float*)d_in[3];
    const float* W0     = (const float*)d_in[4];
    const float* b0     = (const float*)d_in[5];
    const float* W1     = (const float*)d_in[6];
    const float* b1     = (const float*)d_in[7];
    const float* W2     = (const float*)d_in[8];
    const float* b2     = (const float*)d_in[9];
    const float* logvar = (const float*)d_in[10];
    float* out = (float*)d_out;

    {
        int total = D_TOT * D_TOT * HID;
        init_kernel<<<(total + 255) / 256, 256>>>(mp, W0, logvar, out);
    }
    latent_kernel<<<(BATCH * DZ) / 256, 256>>>(z, u, W0, b0, W1, b1, W2, b2, logvar, out);
    {
        dim3 grid(8, 32);   // 8 k-tiles of 32 (k=64..319), 32 b-tiles of 32
        dense_kernel<<<grid, 256>>>(x, z, u, b0, W1, b1, W2, b2, logvar, out);
    }
    finalize_kernel<<<1, 32>>>(out);
}

// round 2
// speedup vs baseline: 1.5381x; 1.5381x over previous
#include <cuda_runtime.h>
#include <math.h>

#define D_TOT 320
#define DZ    64
#define DX    256
#define DK    256          // dense k count (D_TOT - DZ)
#define HID   16
#define BATCH 1024
#define NEG   0.01f
#define HALF_LOG2PI 0.91893853320467274f

// scratch (device globals — no allocation allowed)
__device__ float g_E[D_TOT * D_TOT];                 // exp(-mask_param), [j][k]
__device__ float4 g_W0t[D_TOT * 4 * DK];             // W0 transposed: [j][h4][k'] float4, diag zeroed
__device__ float g_accum;                            // recons accumulator

__device__ __forceinline__ float lrelu(float v) { return fmaxf(v, NEG * v); }

__device__ __forceinline__ unsigned long long pack2(float lo, float hi) {
    unsigned long long r;
    asm("mov.b64 %0, {%1, %2};" : "=l"(r) : "f"(lo), "f"(hi));
    return r;
}
__device__ __forceinline__ void unpack2(unsigned long long v, float& lo, float& hi) {
    asm("mov.b64 {%0, %1}, %2;" : "=f"(lo), "=f"(hi) : "l"(v));
}
__device__ __forceinline__ void ffma2(unsigned long long& d, unsigned long long a,
                                      unsigned long long b) {
    asm("fma.rn.f32x2 %0, %1, %2, %0;" : "+l"(d) : "l"(a), "l"(b));
}

// ---------------------------------------------------------------------------
// Init: E = exp(-mask_param); W0 transpose to [j][h4][k'] with diag zeroed;
// std -> out; zero accumulator.
// ---------------------------------------------------------------------------
__global__ void init_kernel(const float* __restrict__ mp,
                            const float* __restrict__ W0,
                            const float* __restrict__ logvar,
                            float* __restrict__ out) {
    int i = blockIdx.x * blockDim.x + threadIdx.x;

    // W0 transpose: i indexes float4 output slots, total 320*4*256 = 327680
    if (i < D_TOT * 4 * DK) {
        int kp = i & (DK - 1);           // k' 0..255
        int h4 = (i >> 8) & 3;           // which float4 of the 16 h's
        int j  = i >> 10;                // 0..319
        int k  = DZ + kp;
        float4 v;
        if (j == k) {
            v = make_float4(0.f, 0.f, 0.f, 0.f);
        } else {
            v = *(const float4*)(W0 + ((size_t)k * D_TOT + j) * HID + h4 * 4);
        }
        g_W0t[i] = v;
    }
    if (i < D_TOT * D_TOT) g_E[i] = expf(-mp[i]);
    if (i < D_TOT) out[1 + BATCH * D_TOT + i] = expf(0.5f * logvar[i]);
    if (i == 0) g_accum = 0.0f;
}

// ---------------------------------------------------------------------------
// Latent path: k < 64, only j == k contributes (fixed-mask self-link)
// ---------------------------------------------------------------------------
__global__ void latent_kernel(const float* __restrict__ z,
                              const float* __restrict__ u,
                              const float* __restrict__ W0,
                              const float* __restrict__ b0,
                              const float* __restrict__ W1,
                              const float* __restrict__ b1,
                              const float* __restrict__ W2,
                              const float* __restrict__ b2,
                              const float* __restrict__ logvar,
                              float* __restrict__ out) {
    int tid = blockIdx.x * blockDim.x + threadIdx.x;   // 65536 = 1024*64
    int k = tid & (DZ - 1);
    int b = tid >> 6;

    float uu = u[((size_t)b * D_TOT + k) * D_TOT + k];
    float E  = g_E[k * D_TOT + k];
    float s  = z[b * DZ + k];
    float denom = fmaf(1.0f - uu, E, uu);
    float m = __fdividef(uu * s, denom);

    float h1v[HID];
#pragma unroll
    for (int g = 0; g < HID; g++) h1v[g] = b1[k * HID + g];
#pragma unroll
    for (int h = 0; h < HID; h++) {
        float h0 = fmaf(m, W0[((size_t)k * D_TOT + k) * HID + h], b0[k * HID + h]);
        float a = lrelu(h0);
        const float* w1r = W1 + (k * HID + h) * HID;
#pragma unroll
        for (int g = 0; g < HID; g++) h1v[g] = fmaf(a, w1r[g], h1v[g]);
    }
    float mu = b2[k];
#pragma unroll
    for (int h = 0; h < HID; h++) mu = fmaf(lrelu(h1v[h]), W2[k * HID + h], mu);

    out[1 + (size_t)b * D_TOT + k] = mu;

    float logstd = 0.5f * logvar[k];
    float istd = __expf(-logstd);
    float diff = (s - mu) * istd;
    float lp = fmaf(-0.5f * diff, diff, -logstd - HALF_LOG2PI);

#pragma unroll
    for (int o = 16; o > 0; o >>= 1) lp += __shfl_down_sync(0xffffffffu, lp, o);
    if ((threadIdx.x & 31) == 0) atomicAdd(&g_accum, lp);
}

// ---------------------------------------------------------------------------
// Dense path: k in [64, 320). Block: 32 k' (lanes) x 32 b (8 warps x 4 b/thr)
// W0 read from transposed layout (coalesced LDG.128), inner FMA via f32x2.
// ---------------------------------------------------------------------------
__global__ void __launch_bounds__(256, 2)
dense_kernel(const float* __restrict__ x,
             const float* __restrict__ z,
             const float* __restrict__ u,
             const float* __restrict__ b0,
             const float* __restrict__ W1,
             const float* __restrict__ b1,
             const float* __restrict__ W2,
             const float* __restrict__ b2,
             const float* __restrict__ logvar,
             float* __restrict__ out) {
    __shared__ float ss[32 * D_TOT];            // all_var for this block's 32 b's

    int tid  = threadIdx.x;
    int lane = tid & 31;
    int warp = tid >> 5;
    int kp = blockIdx.x * 32 + lane;            // k' in [0,256)
    int k  = DZ + kp;
    int bbase = blockIdx.y * 32 + warp * 4;     // 4 consecutive b's per thread

    // stage all_var = concat(z, x) into smem (coalesced gmem reads)
    for (int idx = tid; idx < 32 * D_TOT; idx += 256) {
        int bl = idx / D_TOT;
        int j  = idx - bl * D_TOT;
        int b  = blockIdx.y * 32 + bl;
        ss[idx] = (j < DZ) ? z[b * DZ + j] : x[b * DX + (j - DZ)];
    }
    __syncthreads();

    unsigned long long acc[4][8];
#pragma unroll
    for (int h2 = 0; h2 < 8; h2++) {
        float lo = b0[k * HID + 2 * h2];
        float hi = b0[k * HID + 2 * h2 + 1];
        unsigned long long p = pack2(lo, hi);
#pragma unroll
        for (int i = 0; i < 4; i++) acc[i][h2] = p;
    }

    const float* srow = &ss[(warp * 4) * D_TOT];
    const float4* Wt = g_W0t + kp;              // + (j*4 + h4)*256
    const float* pu0 = u + ((size_t)(bbase + 0) * D_TOT) * D_TOT + k;
    const float* pu1 = u + ((size_t)(bbase + 1) * D_TOT) * D_TOT + k;
    const float* pu2 = u + ((size_t)(bbase + 2) * D_TOT) * D_TOT + k;
    const float* pu3 = u + ((size_t)(bbase + 3) * D_TOT) * D_TOT + k;

    for (int j0 = 0; j0 < D_TOT; j0 += 16) {
#pragma unroll 4
        for (int jj = 0; jj < 16; jj++) {
            int j = j0 + jj;
            float E = g_E[j * D_TOT + k];

            unsigned long long w[8];
            {
                float4 q;
                q = Wt[(j * 4 + 0) * DK]; w[0] = pack2(q.x, q.y); w[1] = pack2(q.z, q.w);
                q = Wt[(j * 4 + 1) * DK]; w[2] = pack2(q.x, q.y); w[3] = pack2(q.z, q.w);
                q = Wt[(j * 4 + 2) * DK]; w[4] = pack2(q.x, q.y); w[5] = pack2(q.z, q.w);
                q = Wt[(j * 4 + 3) * DK]; w[6] = pack2(q.x, q.y); w[7] = pack2(q.z, q.w);
            }
            const float* pus[4] = {pu0, pu1, pu2, pu3};
#pragma unroll
            for (int i = 0; i < 4; i++) {
                float sj = srow[i * D_TOT + j];
                float uu = __ldcs(pus[i] + (size_t)j * D_TOT);
                float denom = fmaf(1.0f - uu, E, uu);
                float m = __fdividef(uu * sj, denom);
                unsigned long long mm = pack2(m, m);
#pragma unroll
                for (int h2 = 0; h2 < 8; h2++) ffma2(acc[i][h2], mm, w[h2]);
            }
        }
        __syncthreads();   // keep warps' W0t/E window hot in L1
    }

    // epilogue: layers 1 & 2, mu, logp
    float logstd = 0.5f * logvar[k];
    float istd = __expf(-logstd);
    float lpsum = 0.0f;

#pragma unroll
    for (int i = 0; i < 4; i++) {
        float a0[HID];
#pragma unroll
        for (int h2 = 0; h2 < 8; h2++) unpack2(acc[i][h2], a0[2 * h2], a0[2 * h2 + 1]);

        float h1v[HID];
#pragma unroll
        for (int g = 0; g < HID; g++) h1v[g] = b1[k * HID + g];
#pragma unroll
        for (int h = 0; h < HID; h++) {
            float a = lrelu(a0[h]);
            const float4* w1p = (const float4*)(W1 + ((size_t)k * HID + h) * HID);
            float4 r0 = w1p[0], r1 = w1p[1], r2 = w1p[2], r3 = w1p[3];
            float wr[HID] = {r0.x, r0.y, r0.z, r0.w, r1.x, r1.y, r1.z, r1.w,
                             r2.x, r2.y, r2.z, r2.w, r3.x, r3.y, r3.z, r3.w};
#pragma unroll
            for (int g = 0; g < HID; g++) h1v[g] = fmaf(a, wr[g], h1v[g]);
        }
        float mu = b2[k];
#pragma unroll
        for (int h = 0; h < HID; h++) mu = fmaf(lrelu(h1v[h]), W2[k * HID + h], mu);

        int b = bbase + i;
        out[1 + (size_t)b * D_TOT + k] = mu;

        float sk = ss[(warp * 4 + i) * D_TOT + k];
        float diff = (sk - mu) * istd;
        lpsum += fmaf(-0.5f * diff, diff, -logstd - HALF_LOG2PI);
    }

#pragma unroll
    for (int o = 16; o > 0; o >>= 1) lpsum += __shfl_down_sync(0xffffffffu, lpsum, o);
    if (lane == 0) atomicAdd(&g_accum, lpsum);
}

// ---------------------------------------------------------------------------
__global__ void finalize_kernel(float* __restrict__ out) {
    if (threadIdx.x == 0 && blockIdx.x == 0)
        out[0] = g_accum * (1.0f / (float)BATCH);
}

// ---------------------------------------------------------------------------
extern "C" void kernel_launch(void* const* d_in, const int* in_sizes, int n_in,
                              void* d_out, int out_size) {
    const float* x      = (const float*)d_in[0];
    const float* z      = (const float*)d_in[1];
    const float* u      = (const float*)d_in[2];
    const float* mp     = (const float*)d_in[3];
    const float* W0     = (const float*)d_in[4];
    const float* b0     = (const float*)d_in[5];
    const float* W1     = (const float*)d_in[6];
    const float* b1     = (const float*)d_in[7];
    const float* W2     = (const float*)d_in[8];
    const float* b2     = (const float*)d_in[9];
    const float* logvar = (const float*)d_in[10];
    float* out = (float*)d_out;

    {
        int total = D_TOT * 4 * DK;   // 327680 threads covers all init work
        init_kernel<<<(total + 255) / 256, 256>>>(mp, W0, logvar, out);
    }
    latent_kernel<<<(BATCH * DZ) / 256, 256>>>(z, u, W0, b0, W1, b1, W2, b2, logvar, out);
    {
        dim3 grid(8, 32);   // 8 k-tiles of 32 (k=64..319), 32 b-tiles of 32
        dense_kernel<<<grid, 256>>>(x, z, u, b0, W1, b1, W2, b2, logvar, out);
    }
    finalize_kernel<<<1, 32>>>(out);
}